// round 16
// baseline (speedup 1.0000x reference)
#include <cuda_runtime.h>
#include <math.h>

// Problem constants
#define NSEQ 32
#define NHEAD 32
#define NKV 8
#define HPG 4            // heads per kv head (GQA)
#define DH 128           // head size
#define BS 16            // tokens per block
#define MAXB 256         // max blocks per seq
#define CB 16            // blocks per chunk
#define CT (CB * BS)     // 256 tokens per chunk
#define NCHUNK 16
#define QK_SCALE 0.08838834764831845f
#define RPITCH 10        // padded pitch for partial-reduction smem

// Split-KV partial scratch (allocation-free: __device__ globals)
__device__ float  g_pacc[NSEQ * NKV * NCHUNK * HPG * DH];   // 8 MB
__device__ float2 g_pml [NSEQ * NKV * NCHUNK * HPG];
__device__ int    g_done[NSEQ * NKV];                       // arrival counters (self-resetting)

__global__ __launch_bounds__(256, 3) void pa_chunk_kernel(
    const float* __restrict__ q,    // [S, 32, 128]
    const float* __restrict__ kc,   // [NB, 8, 16, 16, 8]  per (b,g): 2048 contig floats
    const float* __restrict__ vc,   // [NB, 8, 128, 16]    per (b,g): 2048 contig floats
    const int*   __restrict__ bt,   // [S, 256]
    const int*   __restrict__ cl,   // [S]
    float* __restrict__ out)        // [S, 32, 128]
{
    const int c = blockIdx.x, g = blockIdx.y, s = blockIdx.z;   // R12 order (proven)
    const int len = cl[s];
    if (c * CT >= len) return;
    const int n_tok = min(len - c * CT, CT);
    const int n_blk = (n_tok + BS - 1) / BS;
    const int tid = threadIdx.x;
    const int w = tid >> 5, l = tid & 31;

    __shared__ __align__(16) float q_s[HPG * DH];            // 2 KB
    __shared__ __align__(16) float ls[HPG * CT];             // 4 KB: probs
    __shared__ __align__(16) float red_s[1024 * RPITCH];     // 40 KB partials (16-blk group)
    __shared__ float red[8], red2[8];
    __shared__ int bt_s[CB];                                 // PRE-SCALED float offsets
    __shared__ int rank_s;

    // pre-scaled: float offset of (block, g) slab within kc/vc (identical layouts)
    if (tid < CB) bt_s[tid] = bt[s * MAXB + c * CB + tid] * 16384 + g * 2048;
    if (tid < 128)  // 512 floats of Q, coalesced float4
        ((float4*)q_s)[tid] =
            ((const float4*)(q + ((size_t)s * NHEAD + g * HPG) * DH))[tid];
    __syncthreads();

    // V-phase lane mapping (declared early: prologue is issued before the softmax)
    const int tl = (l & 3) * 4;
    const int d0 = w * 16 + (l >> 2);
    const int voff = w * 256 + l * 4;
    float4 vb[4][2];

    // ===== Phase 1: K stream, lane-contiguous LDGs, 4-deep pipeline,
    //       two blocks per Q fetch; partials land in red_s (no reduce pass —
    //       the softmax sums the 8 warp-partials directly) ===================
    // Warp w owns K rows 2w,2w+1 of every block (2 contiguous 512B LDG.128s).
    // Lane l holds token l>>1, dims {16w+(l&1)*4..+4} U {16w+8+(l&1)*4..+4}.
    {
        const int koff = w * 256 + l * 4;
        const int tok = l >> 1;
        const int dbase = w * 16 + (l & 1) * 4;

        float4 kb[4][2];
#pragma unroll
        for (int p = 0; p < 4; p++) {
            if (p < n_blk) {
                const float* sp = kc + bt_s[p] + koff;
                kb[p][0] = *(const float4*)sp;
                kb[p][1] = *(const float4*)(sp + 128);
            }
        }

#pragma unroll 1
        for (int gi = 0; gi < n_blk; gi += 8) {
#pragma unroll
            for (int pp = 0; pp < 4; pp++) {      // pairs of blocks
                const int u0 = gi + pp * 2;
                const int u1 = u0 + 1;
                if (u0 < n_blk) {
                    const int s0 = (pp * 2) & 3, s1 = (pp * 2 + 1) & 3;
                    const bool hasB = (u1 < n_blk);
                    const float4 a0 = kb[s0][0], a1 = kb[s0][1];
                    const float4 b0 = kb[s1][0], b1 = kb[s1][1];
                    // prefetch replacements for the consumed slots
                    {
                        const int np0 = u0 + 4;
                        if (np0 < n_blk) {
                            const float* sp = kc + bt_s[np0] + koff;
                            kb[s0][0] = *(const float4*)sp;
                            kb[s0][1] = *(const float4*)(sp + 128);
                        }
                        const int np1 = u1 + 4;
                        if (np1 < n_blk) {
                            const float* sp = kc + bt_s[np1] + koff;
                            kb[s1][0] = *(const float4*)sp;
                            kb[s1][1] = *(const float4*)(sp + 128);
                        }
                    }
#pragma unroll
                    for (int h = 0; h < HPG; h++) {
                        const float4 q0 = *(const float4*)&q_s[h * DH + dbase];
                        const float4 q1 = *(const float4*)&q_s[h * DH + dbase + 8];
                        float tA = 0.f;
                        tA = fmaf(a0.x, q0.x, tA); tA = fmaf(a0.y, q0.y, tA);
                        tA = fmaf(a0.z, q0.z, tA); tA = fmaf(a0.w, q0.w, tA);
                        tA = fmaf(a1.x, q1.x, tA); tA = fmaf(a1.y, q1.y, tA);
                        tA = fmaf(a1.z, q1.z, tA); tA = fmaf(a1.w, q1.w, tA);
                        float tB = 0.f;
                        tB = fmaf(b0.x, q0.x, tB); tB = fmaf(b0.y, q0.y, tB);
                        tB = fmaf(b0.z, q0.z, tB); tB = fmaf(b0.w, q0.w, tB);
                        tB = fmaf(b1.x, q1.x, tB); tB = fmaf(b1.y, q1.y, tB);
                        tB = fmaf(b1.z, q1.z, tB); tB = fmaf(b1.w, q1.w, tB);
                        tA += __shfl_xor_sync(0xffffffffu, tA, 1);
                        tB += __shfl_xor_sync(0xffffffffu, tB, 1);
                        if ((l & 1) == 0) {
                            red_s[((u0 * HPG + h) * BS + tok) * RPITCH + w] = tA;
                            if (hasB)
                                red_s[((u1 * HPG + h) * BS + tok) * RPITCH + w] = tB;
                        }
                    }
                }
            }
        }

        // ===== V prologue HOISTED above the softmax: keeps 16 KB/CTA of loads
        //       in flight through the softmax memory bubble ==================
#pragma unroll
        for (int p = 0; p < 4; p++) {
            if (p < n_blk) {
                const float* sp = vc + bt_s[p] + voff;
                vb[p][0] = *(const float4*)sp;
                vb[p][1] = *(const float4*)(sp + 128);
            }
        }

        __syncthreads();   // red_s complete, visible to all warps
    }

    // ===== Phase 2: softmax; logits summed directly from red_s ==============
    const int h2 = tid >> 6;   // head (64 threads each)
    const int t2 = tid & 63;
    {
        float vals[4];
        float lmax = -1e30f;
#pragma unroll
        for (int k = 0; k < 4; k++) {
            const int tok = t2 + 64 * k;
            float v = -1e30f;
            if (tok < n_tok) {
                const int blk = tok >> 4, tk = tok & 15;
                const float* rp = &red_s[((blk * HPG + h2) * BS + tk) * RPITCH];
                const float2 s0 = *(const float2*)rp;
                const float2 s1 = *(const float2*)(rp + 2);
                const float2 s2 = *(const float2*)(rp + 4);
                const float2 s3 = *(const float2*)(rp + 6);
                v = (((s0.x + s0.y) + (s1.x + s1.y)) +
                     ((s2.x + s2.y) + (s3.x + s3.y))) * QK_SCALE;
            }
            vals[k] = v;
            lmax = fmaxf(lmax, v);
        }
#pragma unroll
        for (int o = 1; o < 32; o <<= 1)
            lmax = fmaxf(lmax, __shfl_xor_sync(0xffffffffu, lmax, o));
        if ((tid & 31) == 0) red[tid >> 5] = lmax;
        __syncthreads();
        const float m = fmaxf(red[h2 * 2], red[h2 * 2 + 1]);
        float lsum = 0.f;
#pragma unroll
        for (int k = 0; k < 4; k++) {
            const int tok = t2 + 64 * k;
            const float p = (tok < n_tok) ? __expf(vals[k] - m) : 0.f;
            ls[h2 * CT + tok] = p;
            lsum += p;
        }
#pragma unroll
        for (int o = 1; o < 32; o <<= 1)
            lsum += __shfl_xor_sync(0xffffffffu, lsum, o);
        if ((tid & 31) == 0) red2[tid >> 5] = lsum;
        __syncthreads();  // probs + red2 visible to all
        if (t2 == 0) {
            const int base = ((s * NKV + g) * NCHUNK + c) * HPG;
            g_pml[base + h2] = make_float2(m, red2[h2 * 2] + red2[h2 * 2 + 1]);
        }
    }

    // ===== Phase 3: V stream, lane-contiguous, 4-block register pipeline ====
    // Warp w owns dims d0 and d0+8; lane covers tokens (l&3)*4..+4.
    {
        float acc[HPG][2] = {};
        int i = 0;
#pragma unroll 1
        for (; i + 4 <= n_blk; i += 4) {
#pragma unroll
            for (int u = 0; u < 4; u++) {
                const float4 a0 = vb[u][0], a1 = vb[u][1];
                const int np = i + u + 4;
                if (np < n_blk) {   // predicated-off: no duplicate tail reads
                    const float* sp = vc + bt_s[np] + voff;
                    vb[u][0] = *(const float4*)sp;
                    vb[u][1] = *(const float4*)(sp + 128);
                }
                const int pbase = (i + u) * BS + tl;
#pragma unroll
                for (int h = 0; h < HPG; h++) {
                    const float4 pv = *(const float4*)&ls[h * CT + pbase];
                    float a = acc[h][0];
                    a = fmaf(a0.x, pv.x, a); a = fmaf(a0.y, pv.y, a);
                    a = fmaf(a0.z, pv.z, a); a = fmaf(a0.w, pv.w, a);
                    acc[h][0] = a;
                    float b = acc[h][1];
                    b = fmaf(a1.x, pv.x, b); b = fmaf(a1.y, pv.y, b);
                    b = fmaf(a1.z, pv.z, b); b = fmaf(a1.w, pv.w, b);
                    acc[h][1] = b;
                }
            }
        }
#pragma unroll
        for (int u = 0; u < 3; u++) {
            if (i + u < n_blk) {
                const float4 a0 = vb[u][0], a1 = vb[u][1];
                const int pbase = (i + u) * BS + tl;
#pragma unroll
                for (int h = 0; h < HPG; h++) {
                    const float4 pv = *(const float4*)&ls[h * CT + pbase];
                    float a = acc[h][0];
                    a = fmaf(a0.x, pv.x, a); a = fmaf(a0.y, pv.y, a);
                    a = fmaf(a0.z, pv.z, a); a = fmaf(a0.w, pv.w, a);
                    acc[h][0] = a;
                    float b = acc[h][1];
                    b = fmaf(a1.x, pv.x, b); b = fmaf(a1.y, pv.y, b);
                    b = fmaf(a1.z, pv.z, b); b = fmaf(a1.w, pv.w, b);
                    acc[h][1] = b;
                }
            }
        }
        const int base = ((s * NKV + g) * NCHUNK + c) * HPG;
#pragma unroll
        for (int h = 0; h < HPG; h++) {
#pragma unroll
            for (int r = 0; r < 2; r++) {
                float v = acc[h][r];
                v += __shfl_xor_sync(0xffffffffu, v, 1);
                v += __shfl_xor_sync(0xffffffffu, v, 2);
                if ((l & 3) == 0)
                    g_pacc[(size_t)(base + h) * DH + d0 + r * 8] = v;
            }
        }
    }

    // ===== Fused combine: last-arriving CTA for (s,g) reduces the partials ==
    __threadfence();   // each thread publishes its pacc/pml writes
    __syncthreads();   // all threads' fences complete before arrival
    if (tid == 0) rank_s = atomicAdd(&g_done[s * NKV + g], 1);
    __syncthreads();

    const int nc = min(NCHUNK, (len + CT - 1) / CT);
    if (rank_s != nc - 1) return;

    __threadfence();   // acquire: order our reads after the observed arrivals
    if (tid == 0) g_done[s * NKV + g] = 0;   // self-reset for next graph replay

    __shared__ float cw_s[HPG][16];
    __shared__ float clinv_s[HPG];
    const int cbase = (s * NKV + g) * NCHUNK;

    if (tid < 128) {   // warp per head computes chunk weights + 1/L
        const int hh = tid >> 5, lane = tid & 31;
        float2 ml = make_float2(-1e30f, 0.f);
        if (lane < nc) ml = g_pml[(cbase + lane) * HPG + hh];
        float M = ml.x;
#pragma unroll
        for (int o = 1; o < 32; o <<= 1)
            M = fmaxf(M, __shfl_xor_sync(0xffffffffu, M, o));
        const float wgt = (lane < nc) ? __expf(ml.x - M) : 0.f;
        float L = ml.y * wgt;
#pragma unroll
        for (int o = 1; o < 32; o <<= 1)
            L += __shfl_xor_sync(0xffffffffu, L, o);
        if (lane < 16) cw_s[hh][lane] = wgt;
        if (lane == 0) clinv_s[hh] = 1.f / L;
    }
    __syncthreads();

    {
        const int d = tid & 127;
        const int h0 = tid >> 7;    // 0 or 1; this thread handles heads h0 and h0+2
#pragma unroll
        for (int rr = 0; rr < 2; rr++) {
            const int hh = h0 + rr * 2;
            float o = 0.f;
#pragma unroll
            for (int cc = 0; cc < NCHUNK; cc++) {
                const float pa = (cc < nc)
                    ? g_pacc[(size_t)((cbase + cc) * HPG + hh) * DH + d] : 0.f;
                o += pa * cw_s[hh][cc];
            }
            out[((size_t)s * NHEAD + g * HPG + hh) * DH + d] = o * clinv_s[hh];
        }
    }
}

extern "C" void kernel_launch(void* const* d_in, const int* in_sizes, int n_in,
                              void* d_out, int out_size)
{
    const float* q  = (const float*)d_in[0];
    const float* kc = (const float*)d_in[1];
    const float* vc = (const float*)d_in[2];
    const int*   bt = (const int*)d_in[3];
    const int*   cl = (const int*)d_in[4];
    float* out = (float*)d_out;

    dim3 grid1(NCHUNK, NKV, NSEQ);   // 16 x 8 x 32 = 4096 CTAs (R12 order)
    pa_chunk_kernel<<<grid1, 256>>>(q, kc, vc, bt, cl, out);
}

// round 17
// speedup vs baseline: 1.0558x; 1.0558x over previous
#include <cuda_runtime.h>
#include <math.h>

// Problem constants
#define NSEQ 32
#define NHEAD 32
#define NKV 8
#define HPG 4            // heads per kv head (GQA)
#define DH 128           // head size
#define BS 16            // tokens per block
#define MAXB 256         // max blocks per seq
#define CB 16            // blocks per chunk
#define CT (CB * BS)     // 256 tokens per chunk
#define NCHUNK 16
#define QK_SCALE 0.08838834764831845f
#define RPITCH 10        // padded pitch for partial-reduction smem

// Split-KV partial scratch (allocation-free: __device__ globals)
__device__ float  g_pacc[NSEQ * NKV * NCHUNK * HPG * DH];   // 8 MB
__device__ float2 g_pml [NSEQ * NKV * NCHUNK * HPG];
__device__ int    g_done[NSEQ * NKV];                       // arrival counters (self-resetting)

__global__ __launch_bounds__(256, 4) void pa_chunk_kernel(
    const float* __restrict__ q,    // [S, 32, 128]
    const float* __restrict__ kc,   // [NB, 8, 16, 16, 8]  per (b,g): 2048 contig floats
    const float* __restrict__ vc,   // [NB, 8, 128, 16]    per (b,g): 2048 contig floats
    const int*   __restrict__ bt,   // [S, 256]
    const int*   __restrict__ cl,   // [S]
    float* __restrict__ out)        // [S, 32, 128]
{
    const int c = blockIdx.x, g = blockIdx.y, s = blockIdx.z;   // R12 order (proven)
    const int len = cl[s];
    if (c * CT >= len) return;
    const int n_tok = min(len - c * CT, CT);
    const int n_blk = (n_tok + BS - 1) / BS;
    const int tid = threadIdx.x;
    const int w = tid >> 5, l = tid & 31;

    __shared__ __align__(16) float q_s[HPG * DH];            // 2 KB
    __shared__ __align__(16) float ls[HPG * CT];             // 4 KB: probs
    __shared__ __align__(16) float red_s[1024 * RPITCH];     // 40 KB partials (16-blk group)
    __shared__ float red[8], red2[8];
    __shared__ int bt_s[CB];                                 // PRE-SCALED float offsets
    __shared__ int rank_s;

    // pre-scaled: float offset of (block, g) slab within kc/vc (identical layouts)
    if (tid < CB) bt_s[tid] = bt[s * MAXB + c * CB + tid] * 16384 + g * 2048;
    if (tid < 128)  // 512 floats of Q, coalesced float4
        ((float4*)q_s)[tid] =
            ((const float4*)(q + ((size_t)s * NHEAD + g * HPG) * DH))[tid];
    __syncthreads();

    // V-phase lane mapping (declared early: prologue is issued before the softmax)
    const int tl = (l & 3) * 4;
    const int d0 = w * 16 + (l >> 2);
    const int voff = w * 256 + l * 4;
    float4 vb[4][2];

    // ===== Phase 1: K stream, lane-contiguous LDGs, 4-deep pipeline,
    //       two blocks per Q fetch, COMPUTE-THEN-PREFETCH (no slot copies —
    //       fits the 64-reg / 4-CTA-per-SM budget);
    //       partials land in red_s (softmax sums them directly) =============
    // Warp w owns K rows 2w,2w+1 of every block (2 contiguous 512B LDG.128s).
    // Lane l holds token l>>1, dims {16w+(l&1)*4..+4} U {16w+8+(l&1)*4..+4}.
    {
        const int koff = w * 256 + l * 4;
        const int tok = l >> 1;
        const int dbase = w * 16 + (l & 1) * 4;

        float4 kb[4][2];
#pragma unroll
        for (int p = 0; p < 4; p++) {
            if (p < n_blk) {
                const float* sp = kc + bt_s[p] + koff;
                kb[p][0] = *(const float4*)sp;
                kb[p][1] = *(const float4*)(sp + 128);
            }
        }

#pragma unroll 1
        for (int gi = 0; gi < n_blk; gi += 8) {
#pragma unroll
            for (int pp = 0; pp < 4; pp++) {      // pairs of blocks
                const int u0 = gi + pp * 2;
                const int u1 = u0 + 1;
                if (u0 < n_blk) {
                    const int s0 = (pp * 2) & 3, s1 = (pp * 2 + 1) & 3;
                    const bool hasB = (u1 < n_blk);
                    // compute directly from the pipeline slots
#pragma unroll
                    for (int h = 0; h < HPG; h++) {
                        const float4 q0 = *(const float4*)&q_s[h * DH + dbase];
                        const float4 q1 = *(const float4*)&q_s[h * DH + dbase + 8];
                        float tA = 0.f;
                        tA = fmaf(kb[s0][0].x, q0.x, tA); tA = fmaf(kb[s0][0].y, q0.y, tA);
                        tA = fmaf(kb[s0][0].z, q0.z, tA); tA = fmaf(kb[s0][0].w, q0.w, tA);
                        tA = fmaf(kb[s0][1].x, q1.x, tA); tA = fmaf(kb[s0][1].y, q1.y, tA);
                        tA = fmaf(kb[s0][1].z, q1.z, tA); tA = fmaf(kb[s0][1].w, q1.w, tA);
                        float tB = 0.f;
                        tB = fmaf(kb[s1][0].x, q0.x, tB); tB = fmaf(kb[s1][0].y, q0.y, tB);
                        tB = fmaf(kb[s1][0].z, q0.z, tB); tB = fmaf(kb[s1][0].w, q0.w, tB);
                        tB = fmaf(kb[s1][1].x, q1.x, tB); tB = fmaf(kb[s1][1].y, q1.y, tB);
                        tB = fmaf(kb[s1][1].z, q1.z, tB); tB = fmaf(kb[s1][1].w, q1.w, tB);
                        tA += __shfl_xor_sync(0xffffffffu, tA, 1);
                        tB += __shfl_xor_sync(0xffffffffu, tB, 1);
                        if ((l & 1) == 0) {
                            red_s[((u0 * HPG + h) * BS + tok) * RPITCH + w] = tA;
                            if (hasB)
                                red_s[((u1 * HPG + h) * BS + tok) * RPITCH + w] = tB;
                        }
                    }
                    // refill the consumed slots for blocks +4 (still ~2 pair-
                    // iterations of latency cover ahead of their use)
                    {
                        const int np0 = u0 + 4;
                        if (np0 < n_blk) {
                            const float* sp = kc + bt_s[np0] + koff;
                            kb[s0][0] = *(const float4*)sp;
                            kb[s0][1] = *(const float4*)(sp + 128);
                        }
                        const int np1 = u1 + 4;
                        if (np1 < n_blk) {
                            const float* sp = kc + bt_s[np1] + koff;
                            kb[s1][0] = *(const float4*)sp;
                            kb[s1][1] = *(const float4*)(sp + 128);
                        }
                    }
                }
            }
        }

        // ===== V prologue HOISTED above the softmax: keeps 16 KB/CTA of loads
        //       in flight through the softmax memory bubble ==================
#pragma unroll
        for (int p = 0; p < 4; p++) {
            if (p < n_blk) {
                const float* sp = vc + bt_s[p] + voff;
                vb[p][0] = *(const float4*)sp;
                vb[p][1] = *(const float4*)(sp + 128);
            }
        }

        __syncthreads();   // red_s complete, visible to all warps
    }

    // ===== Phase 2: softmax; logits summed directly from red_s ==============
    const int h2 = tid >> 6;   // head (64 threads each)
    const int t2 = tid & 63;
    {
        float vals[4];
        float lmax = -1e30f;
#pragma unroll
        for (int k = 0; k < 4; k++) {
            const int tok = t2 + 64 * k;
            float v = -1e30f;
            if (tok < n_tok) {
                const int blk = tok >> 4, tk = tok & 15;
                const float* rp = &red_s[((blk * HPG + h2) * BS + tk) * RPITCH];
                const float2 s0 = *(const float2*)rp;
                const float2 s1 = *(const float2*)(rp + 2);
                const float2 s2 = *(const float2*)(rp + 4);
                const float2 s3 = *(const float2*)(rp + 6);
                v = (((s0.x + s0.y) + (s1.x + s1.y)) +
                     ((s2.x + s2.y) + (s3.x + s3.y))) * QK_SCALE;
            }
            vals[k] = v;
            lmax = fmaxf(lmax, v);
        }
#pragma unroll
        for (int o = 1; o < 32; o <<= 1)
            lmax = fmaxf(lmax, __shfl_xor_sync(0xffffffffu, lmax, o));
        if ((tid & 31) == 0) red[tid >> 5] = lmax;
        __syncthreads();
        const float m = fmaxf(red[h2 * 2], red[h2 * 2 + 1]);
        float lsum = 0.f;
#pragma unroll
        for (int k = 0; k < 4; k++) {
            const int tok = t2 + 64 * k;
            const float p = (tok < n_tok) ? __expf(vals[k] - m) : 0.f;
            ls[h2 * CT + tok] = p;
            lsum += p;
        }
#pragma unroll
        for (int o = 1; o < 32; o <<= 1)
            lsum += __shfl_xor_sync(0xffffffffu, lsum, o);
        if ((tid & 31) == 0) red2[tid >> 5] = lsum;
        __syncthreads();  // probs + red2 visible to all
        if (t2 == 0) {
            const int base = ((s * NKV + g) * NCHUNK + c) * HPG;
            g_pml[base + h2] = make_float2(m, red2[h2 * 2] + red2[h2 * 2 + 1]);
        }
    }

    // ===== Phase 3: V stream, lane-contiguous, 4-block register pipeline,
    //       COMPUTE-THEN-PREFETCH (no slot copies) ===========================
    // Warp w owns dims d0 and d0+8; lane covers tokens (l&3)*4..+4.
    {
        float acc[HPG][2] = {};
        int i = 0;
#pragma unroll 1
        for (; i + 4 <= n_blk; i += 4) {
#pragma unroll
            for (int u = 0; u < 4; u++) {
                const int pbase = (i + u) * BS + tl;
#pragma unroll
                for (int h = 0; h < HPG; h++) {
                    const float4 pv = *(const float4*)&ls[h * CT + pbase];
                    float a = acc[h][0];
                    a = fmaf(vb[u][0].x, pv.x, a); a = fmaf(vb[u][0].y, pv.y, a);
                    a = fmaf(vb[u][0].z, pv.z, a); a = fmaf(vb[u][0].w, pv.w, a);
                    acc[h][0] = a;
                    float b = acc[h][1];
                    b = fmaf(vb[u][1].x, pv.x, b); b = fmaf(vb[u][1].y, pv.y, b);
                    b = fmaf(vb[u][1].z, pv.z, b); b = fmaf(vb[u][1].w, pv.w, b);
                    acc[h][1] = b;
                }
                const int np = i + u + 4;
                if (np < n_blk) {   // refill consumed slot (predicated-off tail)
                    const float* sp = vc + bt_s[np] + voff;
                    vb[u][0] = *(const float4*)sp;
                    vb[u][1] = *(const float4*)(sp + 128);
                }
            }
        }
#pragma unroll
        for (int u = 0; u < 3; u++) {
            if (i + u < n_blk) {
                const int pbase = (i + u) * BS + tl;
#pragma unroll
                for (int h = 0; h < HPG; h++) {
                    const float4 pv = *(const float4*)&ls[h * CT + pbase];
                    float a = acc[h][0];
                    a = fmaf(vb[u][0].x, pv.x, a); a = fmaf(vb[u][0].y, pv.y, a);
                    a = fmaf(vb[u][0].z, pv.z, a); a = fmaf(vb[u][0].w, pv.w, a);
                    acc[h][0] = a;
                    float b = acc[h][1];
                    b = fmaf(vb[u][1].x, pv.x, b); b = fmaf(vb[u][1].y, pv.y, b);
                    b = fmaf(vb[u][1].z, pv.z, b); b = fmaf(vb[u][1].w, pv.w, b);
                    acc[h][1] = b;
                }
            }
        }
        const int base = ((s * NKV + g) * NCHUNK + c) * HPG;
#pragma unroll
        for (int h = 0; h < HPG; h++) {
#pragma unroll
            for (int r = 0; r < 2; r++) {
                float v = acc[h][r];
                v += __shfl_xor_sync(0xffffffffu, v, 1);
                v += __shfl_xor_sync(0xffffffffu, v, 2);
                if ((l & 3) == 0)
                    g_pacc[(size_t)(base + h) * DH + d0 + r * 8] = v;
            }
        }
    }

    // ===== Fused combine: last-arriving CTA for (s,g) reduces the partials ==
    __threadfence();   // each thread publishes its pacc/pml writes
    __syncthreads();   // all threads' fences complete before arrival
    if (tid == 0) rank_s = atomicAdd(&g_done[s * NKV + g], 1);
    __syncthreads();

    const int nc = min(NCHUNK, (len + CT - 1) / CT);
    if (rank_s != nc - 1) return;

    __threadfence();   // acquire: order our reads after the observed arrivals
    if (tid == 0) g_done[s * NKV + g] = 0;   // self-reset for next graph replay

    __shared__ float cw_s[HPG][16];
    __shared__ float clinv_s[HPG];
    const int cbase = (s * NKV + g) * NCHUNK;

    if (tid < 128) {   // warp per head computes chunk weights + 1/L
        const int hh = tid >> 5, lane = tid & 31;
        float2 ml = make_float2(-1e30f, 0.f);
        if (lane < nc) ml = g_pml[(cbase + lane) * HPG + hh];
        float M = ml.x;
#pragma unroll
        for (int o = 1; o < 32; o <<= 1)
            M = fmaxf(M, __shfl_xor_sync(0xffffffffu, M, o));
        const float wgt = (lane < nc) ? __expf(ml.x - M) : 0.f;
        float L = ml.y * wgt;
#pragma unroll
        for (int o = 1; o < 32; o <<= 1)
            L += __shfl_xor_sync(0xffffffffu, L, o);
        if (lane < 16) cw_s[hh][lane] = wgt;
        if (lane == 0) clinv_s[hh] = 1.f / L;
    }
    __syncthreads();

    {
        const int d = tid & 127;
        const int h0 = tid >> 7;    // 0 or 1; this thread handles heads h0 and h0+2
#pragma unroll
        for (int rr = 0; rr < 2; rr++) {
            const int hh = h0 + rr * 2;
            float o = 0.f;
#pragma unroll
            for (int cc = 0; cc < NCHUNK; cc++) {
                const float pa = (cc < nc)
                    ? g_pacc[(size_t)((cbase + cc) * HPG + hh) * DH + d] : 0.f;
                o += pa * cw_s[hh][cc];
            }
            out[((size_t)s * NHEAD + g * HPG + hh) * DH + d] = o * clinv_s[hh];
        }
    }
}

extern "C" void kernel_launch(void* const* d_in, const int* in_sizes, int n_in,
                              void* d_out, int out_size)
{
    const float* q  = (const float*)d_in[0];
    const float* kc = (const float*)d_in[1];
    const float* vc = (const float*)d_in[2];
    const int*   bt = (const int*)d_in[3];
    const int*   cl = (const int*)d_in[4];
    float* out = (float*)d_out;

    dim3 grid1(NCHUNK, NKV, NSEQ);   // 16 x 8 x 32 = 4096 CTAs (R12 order)
    pa_chunk_kernel<<<grid1, 256>>>(q, kc, vc, bt, cl, out);
}